// round 7
// baseline (speedup 1.0000x reference)
#include <cuda_runtime.h>
#include <cstdint>

// ---------------- problem constants ----------------
#define B_    8
#define HW_   4096
#define HDIM_ 64
#define C_    1024
#define M_    32
#define P_    512

// ---------------- GEMM tiling ----------------
#define CTILE   256                 // channels per CTA
#define NBLKS   (C_ / CTILE)        // 4
#define KSPLIT  8                   // K split across grid.z
#define KRANGE  (HW_ / KSPLIT)      // 512 k per CTA
#define KC      16                  // k (pixels) per chunk
#define NCHUNK  (KRANGE / KC)       // 32 chunks per CTA
#define NSTAGE  5

// smem strides (words) — conflict-free fragment LDS, 16B-aligned rows
#define FSW 264                     // F row stride: 256 ch + 8 pad  (264%32=8)
#define WSW 36                      // W row stride: 16 k + 20 pad   (36%32=4)
#define FROWB (FSW * 4)             // 1056
#define WROWB (WSW * 4)             // 144
#define FBYTES (KC * FROWB)         // 16896
#define WBYTES (M_ * WROWB)         // 4608
#define STAGE_BYTES (FBYTES + WBYTES)       // 21504
#define SMEM_TOTAL (NSTAGE * STAGE_BYTES)   // 107520

// Scratch: tf32(RNA)-rounded weights; K-split partials; tile arrival counters
__device__ float g_W[(size_t)B_ * M_ * HW_];
__device__ float g_part[(size_t)KSPLIT * B_ * M_ * C_];
__device__ unsigned int g_cnt[NBLKS * B_];

// ---------------- helpers ----------------
__device__ __forceinline__ uint32_t smem_u32(const void* p) {
    uint32_t a;
    asm("{ .reg .u64 t; cvta.to.shared.u64 t, %1; cvt.u32.u64 %0, t; }" : "=r"(a) : "l"(p));
    return a;
}
__device__ __forceinline__ void cp_async16(uint32_t dst, const void* src) {
    asm volatile("cp.async.cg.shared.global [%0], [%1], 16;" :: "r"(dst), "l"(src));
}
#define CP_COMMIT() asm volatile("cp.async.commit_group;" ::: "memory")
#define CP_WAIT3()  asm volatile("cp.async.wait_group 3;" ::: "memory")

__device__ __forceinline__ uint32_t to_tf32(float x) {
    uint32_t r;
    asm("cvt.rna.tf32.f32 %0, %1;" : "=r"(r) : "f"(x));
    return r;
}

// D[16ch x 8m] += A[16ch x 8k] * B[8k x 8m]   (tf32, fp32 accum)
__device__ __forceinline__ void mma_tf32(float* d,
                                         uint32_t a0, uint32_t a1, uint32_t a2, uint32_t a3,
                                         uint32_t b0, uint32_t b1) {
    asm volatile(
        "mma.sync.aligned.m16n8k8.row.col.f32.tf32.tf32.f32 "
        "{%0,%1,%2,%3}, {%4,%5,%6,%7}, {%8,%9}, {%0,%1,%2,%3};"
        : "+f"(d[0]), "+f"(d[1]), "+f"(d[2]), "+f"(d[3])
        : "r"(a0), "r"(a1), "r"(a2), "r"(a3), "r"(b0), "r"(b1));
}

// ---------------------------------------------------------------------------
// Pass 1: per-(b,m) weight histogram over the 64x64 grid, RNA-rounded to tf32.
// ---------------------------------------------------------------------------
__global__ void __launch_bounds__(256) pass1_weights(
    const float* __restrict__ coords)   // [B, M, P, 2]
{
    __shared__ float wloc[HW_];
    const int bm  = blockIdx.x;     // 0..255
    const int tid = threadIdx.x;

    #pragma unroll 4
    for (int i = tid; i < HW_; i += 256) wloc[i] = 0.0f;
    __syncthreads();

    const float* cp = coords + (size_t)bm * P_ * 2;
    const float invP = 1.0f / (float)P_;
    const float s = (float)(HDIM_ - 1);

    for (int p = tid; p < P_; p += 256) {
        float yn = cp[p * 2 + 0];
        float xn = cp[p * 2 + 1];
        float y = yn * s;
        float x = xn * s;
        float x0f = floorf(x), y0f = floorf(y);
        float wx = x - x0f, wy = y - y0f;
        int ix0 = min(max((int)x0f, 0), HDIM_ - 1);
        int ix1 = min(ix0 + 1, HDIM_ - 1);
        int iy0 = min(max((int)y0f, 0), HDIM_ - 1);
        int iy1 = min(iy0 + 1, HDIM_ - 1);
        float w00 = (1.0f - wx) * (1.0f - wy) * invP;
        float w01 = wx * (1.0f - wy) * invP;
        float w10 = (1.0f - wx) * wy * invP;
        float w11 = wx * wy * invP;
        atomicAdd(&wloc[iy0 * HDIM_ + ix0], w00);
        atomicAdd(&wloc[iy0 * HDIM_ + ix1], w01);
        atomicAdd(&wloc[iy1 * HDIM_ + ix0], w10);
        atomicAdd(&wloc[iy1 * HDIM_ + ix1], w11);
    }
    __syncthreads();

    float* wout = g_W + (size_t)bm * HW_;
    #pragma unroll 4
    for (int i = tid; i < HW_; i += 256) {
        wout[i] = __uint_as_float(to_tf32(wloc[i]));
    }
}

// ---------------------------------------------------------------------------
// Pass 2: tf32 HMMA GEMM + fused K-split reduction.
// CTA (nblk, b, ksp): partial D[32m x 256ch] over 512 k -> g_part.
// Last-arriving CTA per (nblk,b) tile reduces the 8 partials into d_out.
// ---------------------------------------------------------------------------
__global__ void __launch_bounds__(256, 2) pass2_mma(
    const float* __restrict__ F,        // [B, HW, C]
    float* __restrict__ out)            // [B, M, 1, C]
{
    extern __shared__ char smem[];
    const uint32_t sbase = smem_u32(smem);

    const int tid  = threadIdx.x;
    const int lane = tid & 31;
    const int wid  = tid >> 5;          // 0..7
    const int nblk = blockIdx.x;        // 0..3
    const int b    = blockIdx.y;        // 0..7
    const int ksp  = blockIdx.z;        // 0..7
    const int c0   = nblk * CTILE;
    const int kbase = ksp * KRANGE;

    const int r = lane >> 2;            // 0..7
    const int c = lane & 3;             // 0..3
    const int chw = wid * 32;           // warp channel base within tile

    const float* Fb = F + ((size_t)b * HW_ + kbase) * C_ + c0;
    const float* Wb = g_W + (size_t)b * M_ * HW_ + kbase;

    // ---- chunk loader: F tile [16k x 256ch] + W tile [32m x 16k] ----
    auto load_chunk = [&](int chunk) {
        const int s  = chunk % NSTAGE;
        const int k0 = chunk * KC;
        const uint32_t fb = sbase + s * STAGE_BYTES;
        const uint32_t wb = fb + FBYTES;
        // F: 1024 x 16B units
        #pragma unroll
        for (int h = 0; h < 4; h++) {
            int unit = tid + h * 256;
            int row = unit >> 6;        // local k 0..15
            int uc  = unit & 63;        // 16B unit within 256-ch row
            cp_async16(fb + (uint32_t)(row * FROWB + uc * 16),
                       Fb + (size_t)(k0 + row) * C_ + uc * 4);
        }
        // W: 128 x 16B units (threads 0..127)
        if (tid < 128) {
            int m  = tid >> 2;
            int kq = tid & 3;
            cp_async16(wb + (uint32_t)(m * WROWB + kq * 16),
                       Wb + (size_t)m * HW_ + k0 + kq * 4);
        }
    };

    // prologue: 4 chunks in flight
    load_chunk(0); CP_COMMIT();
    load_chunk(1); CP_COMMIT();
    load_chunk(2); CP_COMMIT();
    load_chunk(3); CP_COMMIT();

    float d[2][4][4];
    #pragma unroll
    for (int t = 0; t < 2; t++)
        #pragma unroll
        for (int j = 0; j < 4; j++)
            #pragma unroll
            for (int e = 0; e < 4; e++) d[t][j][e] = 0.f;

    for (int i = 0; i < NCHUNK; i++) {
        CP_WAIT3();                 // chunk i resident
        __syncthreads();

        const float* fptr = reinterpret_cast<const float*>(smem + (i % NSTAGE) * STAGE_BYTES);
        const float* wptr = fptr + KC * FSW;

        #pragma unroll
        for (int ks = 0; ks < KC / 8; ks++) {
            const int kr = ks * 8;
            // A = F fragments: 2 sets of 16 ch
            uint32_t a[2][4];
            #pragma unroll
            for (int t = 0; t < 2; t++) {
                const int chb = chw + t * 16;
                a[t][0] = to_tf32(fptr[(kr + c) * FSW + chb + r]);
                a[t][1] = to_tf32(fptr[(kr + c) * FSW + chb + r + 8]);
                a[t][2] = to_tf32(fptr[(kr + c + 4) * FSW + chb + r]);
                a[t][3] = to_tf32(fptr[(kr + c + 4) * FSW + chb + r + 8]);
            }
            // B = W fragments: 4 sets of 8 m (already tf32 from pass1)
            uint32_t bf[4][2];
            #pragma unroll
            for (int j = 0; j < 4; j++) {
                bf[j][0] = __float_as_uint(wptr[(j * 8 + r) * WSW + kr + c]);
                bf[j][1] = __float_as_uint(wptr[(j * 8 + r) * WSW + kr + c + 4]);
            }
            #pragma unroll
            for (int t = 0; t < 2; t++)
                #pragma unroll
                for (int j = 0; j < 4; j++)
                    mma_tf32(d[t][j], a[t][0], a[t][1], a[t][2], a[t][3],
                             bf[j][0], bf[j][1]);
        }

        if (i + 4 < NCHUNK) load_chunk(i + 4);
        CP_COMMIT();                // one group per iteration (may be empty)
    }

    // ---- write partials ----
    // D element map per mma: thread (r,c) holds (ch=r, m=2c), (r, 2c+1), (r+8, 2c), (r+8, 2c+1)
    float* pb = g_part + ((size_t)(ksp * B_ + b)) * M_ * C_ + c0;
    #pragma unroll
    for (int t = 0; t < 2; t++) {
        const int ch = chw + t * 16 + r;
        #pragma unroll
        for (int j = 0; j < 4; j++) {
            int mA = j * 8 + 2 * c, mB = mA + 1;
            pb[(size_t)mA * C_ + ch]     = d[t][j][0];
            pb[(size_t)mB * C_ + ch]     = d[t][j][1];
            pb[(size_t)mA * C_ + ch + 8] = d[t][j][2];
            pb[(size_t)mB * C_ + ch + 8] = d[t][j][3];
        }
    }

    // ---- fused reduction: last CTA of this (nblk,b) tile sums the 8 partials
    __threadfence();
    __syncthreads();
    __shared__ unsigned int s_last;
    if (tid == 0) {
        unsigned int old = atomicAdd(&g_cnt[nblk * B_ + b], 1);
        s_last = (old == KSPLIT - 1) ? 1u : 0u;
    }
    __syncthreads();
    if (s_last) {
        __threadfence();            // acquire: make other CTAs' partials visible
        // tile = [b][all 32 m][c0 .. c0+255] : 2048 float4 slots
        const int q4 = CTILE / 4;   // 64 float4 per m-row
        for (int idx = tid; idx < M_ * q4; idx += 256) {
            int m = idx / q4;
            int q = idx % q4;
            size_t off = ((size_t)b * M_ + m) * C_ + c0 + q * 4;
            float4 s = *reinterpret_cast<const float4*>(g_part + off);
            #pragma unroll
            for (int k = 1; k < KSPLIT; k++) {
                float4 v = *reinterpret_cast<const float4*>(
                    g_part + (size_t)k * B_ * M_ * C_ + off);
                s.x += v.x; s.y += v.y; s.z += v.z; s.w += v.w;
            }
            *reinterpret_cast<float4*>(out + off) = s;
        }
        if (tid == 0) g_cnt[nblk * B_ + b] = 0;   // reset for next replay
    }
}

// ---------------------------------------------------------------------------
extern "C" void kernel_launch(void* const* d_in, const int* in_sizes, int n_in,
                              void* d_out, int out_size)
{
    const float* feature = (const float*)d_in[0];
    const float* coords  = (const float*)d_in[1];
    if (n_in >= 2 && in_sizes[0] == B_ * M_ * P_ * 2) {
        feature = (const float*)d_in[1];
        coords  = (const float*)d_in[0];
    }

    cudaFuncSetAttribute(pass2_mma, cudaFuncAttributeMaxDynamicSharedMemorySize, SMEM_TOTAL);

    pass1_weights<<<B_ * M_, 256>>>(coords);

    dim3 g2(NBLKS, B_, KSPLIT);
    pass2_mma<<<g2, 256, SMEM_TOTAL>>>(feature, (float*)d_out);
}

// round 8
// speedup vs baseline: 1.1838x; 1.1838x over previous
#include <cuda_runtime.h>
#include <cstdint>

// ---------------- problem constants ----------------
#define B_    8
#define HW_   4096
#define HDIM_ 64
#define C_    1024
#define M_    32
#define P_    512

// ---------------- GEMM tiling (R6-proven config) ----------------
#define CTILE   256                 // channels per CTA
#define NBLKS   (C_ / CTILE)        // 4
#define KSPLIT  8                   // K split across grid.z
#define KRANGE  (HW_ / KSPLIT)      // 512 k per CTA
#define KC      16                  // k (pixels) per chunk
#define NCHUNK  (KRANGE / KC)       // 32 chunks per CTA
#define NSTAGE  4

// smem strides (words) — conflict-free fragment LDS, 16B-aligned rows
#define FSW 264                     // F row stride: 256 ch + 8 pad  (264%32=8)
#define WSW 36                      // W row stride: 16 k + 20 pad   (36%32=4)
#define FROWB (FSW * 4)             // 1056
#define WROWB (WSW * 4)             // 144
#define FBYTES (KC * FROWB)         // 16896
#define WBYTES (M_ * WROWB)         // 4608
#define STAGE_BYTES (FBYTES + WBYTES)       // 21504
#define SMEM_TOTAL (NSTAGE * STAGE_BYTES)   // 86016

// Scratch: tf32(RNA)-rounded weights; K-split partials
__device__ float g_W[(size_t)B_ * M_ * HW_];
__device__ float g_part[(size_t)KSPLIT * B_ * M_ * C_];

// ---------------- helpers ----------------
__device__ __forceinline__ uint32_t smem_u32(const void* p) {
    uint32_t a;
    asm("{ .reg .u64 t; cvta.to.shared.u64 t, %1; cvt.u32.u64 %0, t; }" : "=r"(a) : "l"(p));
    return a;
}
__device__ __forceinline__ void cp_async16(uint32_t dst, const void* src) {
    asm volatile("cp.async.cg.shared.global [%0], [%1], 16;" :: "r"(dst), "l"(src));
}
#define CP_COMMIT() asm volatile("cp.async.commit_group;" ::: "memory")
#define CP_WAIT2()  asm volatile("cp.async.wait_group 2;" ::: "memory")

#define GRIDDEP_WAIT()    asm volatile("griddepcontrol.wait;" ::: "memory")
#define GRIDDEP_TRIGGER() asm volatile("griddepcontrol.launch_dependents;" ::: "memory")

__device__ __forceinline__ uint32_t to_tf32(float x) {
    uint32_t r;
    asm("cvt.rna.tf32.f32 %0, %1;" : "=r"(r) : "f"(x));
    return r;
}

// D[16ch x 8m] += A[16ch x 8k] * B[8k x 8m]   (tf32, fp32 accum)
__device__ __forceinline__ void mma_tf32(float* d,
                                         uint32_t a0, uint32_t a1, uint32_t a2, uint32_t a3,
                                         uint32_t b0, uint32_t b1) {
    asm volatile(
        "mma.sync.aligned.m16n8k8.row.col.f32.tf32.tf32.f32 "
        "{%0,%1,%2,%3}, {%4,%5,%6,%7}, {%8,%9}, {%0,%1,%2,%3};"
        : "+f"(d[0]), "+f"(d[1]), "+f"(d[2]), "+f"(d[3])
        : "r"(a0), "r"(a1), "r"(a2), "r"(a3), "r"(b0), "r"(b1));
}

// ---------------------------------------------------------------------------
// Pass 1: per-(b,m) weight histogram over the 64x64 grid, RNA-rounded to tf32.
// ---------------------------------------------------------------------------
__global__ void __launch_bounds__(256) pass1_weights(
    const float* __restrict__ coords)   // [B, M, P, 2]
{
    __shared__ float wloc[HW_];
    const int bm  = blockIdx.x;     // 0..255
    const int tid = threadIdx.x;

    #pragma unroll 4
    for (int i = tid; i < HW_; i += 256) wloc[i] = 0.0f;
    __syncthreads();

    const float* cp = coords + (size_t)bm * P_ * 2;
    const float invP = 1.0f / (float)P_;
    const float s = (float)(HDIM_ - 1);

    for (int p = tid; p < P_; p += 256) {
        float yn = cp[p * 2 + 0];
        float xn = cp[p * 2 + 1];
        float y = yn * s;
        float x = xn * s;
        float x0f = floorf(x), y0f = floorf(y);
        float wx = x - x0f, wy = y - y0f;
        int ix0 = min(max((int)x0f, 0), HDIM_ - 1);
        int ix1 = min(ix0 + 1, HDIM_ - 1);
        int iy0 = min(max((int)y0f, 0), HDIM_ - 1);
        int iy1 = min(iy0 + 1, HDIM_ - 1);
        float w00 = (1.0f - wx) * (1.0f - wy) * invP;
        float w01 = wx * (1.0f - wy) * invP;
        float w10 = (1.0f - wx) * wy * invP;
        float w11 = wx * wy * invP;
        atomicAdd(&wloc[iy0 * HDIM_ + ix0], w00);
        atomicAdd(&wloc[iy0 * HDIM_ + ix1], w01);
        atomicAdd(&wloc[iy1 * HDIM_ + ix0], w10);
        atomicAdd(&wloc[iy1 * HDIM_ + ix1], w11);
    }
    __syncthreads();

    float* wout = g_W + (size_t)bm * HW_;
    #pragma unroll 4
    for (int i = tid; i < HW_; i += 256) {
        wout[i] = __uint_as_float(to_tf32(wloc[i]));
    }
    __threadfence();
    GRIDDEP_TRIGGER();              // stores done -> let pass2 read g_W
}

// ---------------------------------------------------------------------------
// Pass 2: tf32 HMMA GEMM, K-split. PDL: F prologue issued before
// griddepcontrol.wait (F does not depend on pass1); W loads after.
// CTA (nblk, b, ksp): partial D[32m x 256ch] over 512 k -> g_part.
// ---------------------------------------------------------------------------
__global__ void __launch_bounds__(256, 2) pass2_mma(
    const float* __restrict__ F)        // [B, HW, C]
{
    extern __shared__ char smem[];
    const uint32_t sbase = smem_u32(smem);

    const int tid  = threadIdx.x;
    const int lane = tid & 31;
    const int wid  = tid >> 5;          // 0..7
    const int nblk = blockIdx.x;        // 0..3
    const int b    = blockIdx.y;        // 0..7
    const int ksp  = blockIdx.z;        // 0..7
    const int c0   = nblk * CTILE;
    const int kbase = ksp * KRANGE;

    const int r = lane >> 2;            // 0..7
    const int c = lane & 3;             // 0..3
    const int chw = wid * 32;           // warp channel base within tile

    const float* Fb = F + ((size_t)b * HW_ + kbase) * C_ + c0;
    const float* Wb = g_W + (size_t)b * M_ * HW_ + kbase;

    // F tile loader: [16k x 256ch]
    auto load_F = [&](int chunk) {
        const int s  = chunk & (NSTAGE - 1);
        const int k0 = chunk * KC;
        const uint32_t fb = sbase + s * STAGE_BYTES;
        #pragma unroll
        for (int h = 0; h < 4; h++) {
            int unit = tid + h * 256;
            int row = unit >> 6;        // local k 0..15
            int uc  = unit & 63;        // 16B unit within 256-ch row
            cp_async16(fb + (uint32_t)(row * FROWB + uc * 16),
                       Fb + (size_t)(k0 + row) * C_ + uc * 4);
        }
    };
    // W tile loader: [32m x 16k]
    auto load_W = [&](int chunk) {
        const int s  = chunk & (NSTAGE - 1);
        const int k0 = chunk * KC;
        const uint32_t wb = sbase + s * STAGE_BYTES + FBYTES;
        if (tid < 128) {
            int m  = tid >> 2;
            int kq = tid & 3;
            cp_async16(wb + (uint32_t)(m * WROWB + kq * 16),
                       Wb + (size_t)m * HW_ + k0 + kq * 4);
        }
    };

    // PDL prologue: F groups first (independent of pass1), then wait, then W.
    load_F(0); CP_COMMIT();
    load_F(1); CP_COMMIT();
    load_F(2); CP_COMMIT();
    GRIDDEP_WAIT();                 // pass1's g_W now visible
    load_W(0); CP_COMMIT();
    load_W(1); CP_COMMIT();
    load_W(2); CP_COMMIT();
    // Group schedule: F0 F1 F2 W0 W1 W2, then one combined group per iter.
    // CP_WAIT2 at iter i always leaves exactly the 2 newest groups pending,
    // so F(i) and W(i) are complete when compute begins.

    float d[2][4][4];
    #pragma unroll
    for (int t = 0; t < 2; t++)
        #pragma unroll
        for (int j = 0; j < 4; j++)
            #pragma unroll
            for (int e = 0; e < 4; e++) d[t][j][e] = 0.f;

    for (int i = 0; i < NCHUNK; i++) {
        CP_WAIT2();                 // chunk i resident
        __syncthreads();

        const float* fptr = reinterpret_cast<const float*>(smem + (i & (NSTAGE - 1)) * STAGE_BYTES);
        const float* wptr = fptr + KC * FSW;

        #pragma unroll
        for (int ks = 0; ks < KC / 8; ks++) {
            const int kr = ks * 8;
            // A = F fragments: 2 sets of 16 ch
            uint32_t a[2][4];
            #pragma unroll
            for (int t = 0; t < 2; t++) {
                const int chb = chw + t * 16;
                a[t][0] = to_tf32(fptr[(kr + c) * FSW + chb + r]);
                a[t][1] = to_tf32(fptr[(kr + c) * FSW + chb + r + 8]);
                a[t][2] = to_tf32(fptr[(kr + c + 4) * FSW + chb + r]);
                a[t][3] = to_tf32(fptr[(kr + c + 4) * FSW + chb + r + 8]);
            }
            // B = W fragments: 4 sets of 8 m (already tf32 from pass1)
            uint32_t bf[4][2];
            #pragma unroll
            for (int j = 0; j < 4; j++) {
                bf[j][0] = __float_as_uint(wptr[(j * 8 + r) * WSW + kr + c]);
                bf[j][1] = __float_as_uint(wptr[(j * 8 + r) * WSW + kr + c + 4]);
            }
            #pragma unroll
            for (int t = 0; t < 2; t++)
                #pragma unroll
                for (int j = 0; j < 4; j++)
                    mma_tf32(d[t][j], a[t][0], a[t][1], a[t][2], a[t][3],
                             bf[j][0], bf[j][1]);
        }

        if (i + 3 < NCHUNK) { load_F(i + 3); load_W(i + 3); }
        CP_COMMIT();                // one group per iteration (may be empty)
    }

    // ---- write partials ----
    // D map per mma: thread (r,c) holds (ch=r, m=2c), (r, 2c+1), (r+8, 2c), (r+8, 2c+1)
    float* pb = g_part + ((size_t)(ksp * B_ + b)) * M_ * C_ + c0;
    #pragma unroll
    for (int t = 0; t < 2; t++) {
        const int ch = chw + t * 16 + r;
        #pragma unroll
        for (int j = 0; j < 4; j++) {
            int mA = j * 8 + 2 * c, mB = mA + 1;
            pb[(size_t)mA * C_ + ch]     = d[t][j][0];
            pb[(size_t)mB * C_ + ch]     = d[t][j][1];
            pb[(size_t)mA * C_ + ch + 8] = d[t][j][2];
            pb[(size_t)mB * C_ + ch + 8] = d[t][j][3];
        }
    }
    __threadfence();
    GRIDDEP_TRIGGER();              // partials done -> let pass3 start
}

// ---------------------------------------------------------------------------
// Pass 3: reduce KSPLIT partials -> d_out  [B, M, 1, C] f32  (full-width)
// ---------------------------------------------------------------------------
__global__ void __launch_bounds__(256) pass3_reduce(float* __restrict__ out)
{
    GRIDDEP_WAIT();
    const int total4 = B_ * M_ * C_ / 4;            // 65536 float4 slots
    int idx = blockIdx.x * 256 + threadIdx.x;
    if (idx >= total4) return;
    const float4* p = reinterpret_cast<const float4*>(g_part);
    float4 s = p[idx];
    #pragma unroll
    for (int k = 1; k < KSPLIT; k++) {
        float4 v = p[(size_t)k * total4 + idx];
        s.x += v.x; s.y += v.y; s.z += v.z; s.w += v.w;
    }
    reinterpret_cast<float4*>(out)[idx] = s;
}

// ---------------------------------------------------------------------------
extern "C" void kernel_launch(void* const* d_in, const int* in_sizes, int n_in,
                              void* d_out, int out_size)
{
    const float* feature = (const float*)d_in[0];
    const float* coords  = (const float*)d_in[1];
    if (n_in >= 2 && in_sizes[0] == B_ * M_ * P_ * 2) {
        feature = (const float*)d_in[1];
        coords  = (const float*)d_in[0];
    }

    static int smem_set = 0;
    if (!smem_set) {
        cudaFuncSetAttribute(pass2_mma, cudaFuncAttributeMaxDynamicSharedMemorySize, SMEM_TOTAL);
        smem_set = 1;
    }

    pass1_weights<<<B_ * M_, 256>>>(coords);

    // pass2: PDL-dependent on pass1
    {
        cudaLaunchConfig_t cfg = {};
        cfg.gridDim  = dim3(NBLKS, B_, KSPLIT);
        cfg.blockDim = dim3(256, 1, 1);
        cfg.dynamicSmemBytes = SMEM_TOTAL;
        cfg.stream = 0;
        cudaLaunchAttribute at[1];
        at[0].id = cudaLaunchAttributeProgrammaticStreamSerialization;
        at[0].val.programmaticStreamSerializationAllowed = 1;
        cfg.attrs = at;
        cfg.numAttrs = 1;
        cudaLaunchKernelEx(&cfg, pass2_mma, feature);
    }

    // pass3: PDL-dependent on pass2
    {
        const int total4 = B_ * M_ * C_ / 4;        // 65536
        cudaLaunchConfig_t cfg = {};
        cfg.gridDim  = dim3((total4 + 255) / 256, 1, 1);
        cfg.blockDim = dim3(256, 1, 1);
        cfg.dynamicSmemBytes = 0;
        cfg.stream = 0;
        cudaLaunchAttribute at[1];
        at[0].id = cudaLaunchAttributeProgrammaticStreamSerialization;
        at[0].val.programmaticStreamSerializationAllowed = 1;
        cfg.attrs = at;
        cfg.numAttrs = 1;
        float* outp = (float*)d_out;
        cudaLaunchKernelEx(&cfg, pass3_reduce, outp);
    }
}

// round 9
// speedup vs baseline: 1.2310x; 1.0399x over previous
#include <cuda_runtime.h>
#include <cstdint>

// ---------------- problem constants ----------------
#define B_    8
#define HW_   4096
#define HDIM_ 64
#define C_    1024
#define M_    32
#define P_    512

// ---------------- GEMM tiling (R6-proven config) ----------------
#define CTILE   256                 // channels per CTA
#define NBLKS   (C_ / CTILE)        // 4
#define KSPLIT  8                   // K split across grid.z
#define KRANGE  (HW_ / KSPLIT)      // 512 k per CTA
#define KC      16                  // k (pixels) per chunk
#define NCHUNK  (KRANGE / KC)       // 32 chunks per CTA
#define NSTAGE  4
#define NCTAS   (NBLKS * B_ * KSPLIT)   // 256 == B_*M_ (one histogram per CTA)

// smem strides (words) — conflict-free fragment LDS, 16B-aligned rows
#define FSW 264                     // F row stride: 256 ch + 8 pad  (264%32=8)
#define WSW 36                      // W row stride: 16 k + 20 pad   (36%32=4)
#define FROWB (FSW * 4)             // 1056
#define WROWB (WSW * 4)             // 144
#define FBYTES (KC * FROWB)         // 16896
#define WBYTES (M_ * WROWB)         // 4608
#define STAGE_BYTES (FBYTES + WBYTES)       // 21504
#define SMEM_TOTAL (NSTAGE * STAGE_BYTES)   // 86016

// Scratch: tf32(RNA)-rounded weights; K-split partials; global barrier
__device__ float g_W[(size_t)B_ * M_ * HW_];
__device__ float g_part[(size_t)KSPLIT * B_ * M_ * C_];
__device__ unsigned int g_bar;      // reset by pass3 each call

// ---------------- helpers ----------------
__device__ __forceinline__ uint32_t smem_u32(const void* p) {
    uint32_t a;
    asm("{ .reg .u64 t; cvta.to.shared.u64 t, %1; cvt.u32.u64 %0, t; }" : "=r"(a) : "l"(p));
    return a;
}
__device__ __forceinline__ void cp_async16(uint32_t dst, const void* src) {
    asm volatile("cp.async.cg.shared.global [%0], [%1], 16;" :: "r"(dst), "l"(src));
}
#define CP_COMMIT() asm volatile("cp.async.commit_group;" ::: "memory")
#define CP_WAIT2()  asm volatile("cp.async.wait_group 2;" ::: "memory")

__device__ __forceinline__ uint32_t to_tf32(float x) {
    uint32_t r;
    asm("cvt.rna.tf32.f32 %0, %1;" : "=r"(r) : "f"(x));
    return r;
}

// D[16ch x 8m] += A[16ch x 8k] * B[8k x 8m]   (tf32, fp32 accum)
__device__ __forceinline__ void mma_tf32(float* d,
                                         uint32_t a0, uint32_t a1, uint32_t a2, uint32_t a3,
                                         uint32_t b0, uint32_t b1) {
    asm volatile(
        "mma.sync.aligned.m16n8k8.row.col.f32.tf32.tf32.f32 "
        "{%0,%1,%2,%3}, {%4,%5,%6,%7}, {%8,%9}, {%0,%1,%2,%3};"
        : "+f"(d[0]), "+f"(d[1]), "+f"(d[2]), "+f"(d[3])
        : "r"(a0), "r"(a1), "r"(a2), "r"(a3), "r"(b0), "r"(b1));
}

// ---------------------------------------------------------------------------
// Fused kernel: phase A (one (b,m) weight histogram per CTA) -> device-wide
// barrier -> phase B (tf32 HMMA GEMM over K-split).
// Grid = 256 CTAs, 2/SM x 148 SM = 296 slots: single wave, barrier is safe.
// ---------------------------------------------------------------------------
__global__ void __launch_bounds__(256, 2) fused_mma(
    const float* __restrict__ coords,   // [B, M, P, 2]
    const float* __restrict__ F)        // [B, HW, C]
{
    extern __shared__ char smem[];
    const uint32_t sbase = smem_u32(smem);

    const int tid  = threadIdx.x;
    const int lane = tid & 31;
    const int wid  = tid >> 5;          // 0..7
    const int nblk = blockIdx.x;        // 0..3
    const int b    = blockIdx.y;        // 0..7
    const int ksp  = blockIdx.z;        // 0..7
    const int c0   = nblk * CTILE;
    const int kbase = ksp * KRANGE;

    const float* Fb = F + ((size_t)b * HW_ + kbase) * C_ + c0;
    const float* Wb = g_W + (size_t)b * M_ * HW_ + kbase;

    // F tile loader: [16k x 256ch]
    auto load_F = [&](int chunk) {
        const int s  = chunk & (NSTAGE - 1);
        const int k0 = chunk * KC;
        const uint32_t fb = sbase + s * STAGE_BYTES;
        #pragma unroll
        for (int h = 0; h < 4; h++) {
            int unit = tid + h * 256;
            int row = unit >> 6;        // local k 0..15
            int uc  = unit & 63;        // 16B unit within 256-ch row
            cp_async16(fb + (uint32_t)(row * FROWB + uc * 16),
                       Fb + (size_t)(k0 + row) * C_ + uc * 4);
        }
    };
    // W tile loader: [32m x 16k]
    auto load_W = [&](int chunk) {
        const int s  = chunk & (NSTAGE - 1);
        const int k0 = chunk * KC;
        const uint32_t wb = sbase + s * STAGE_BYTES + FBYTES;
        if (tid < 128) {
            int m  = tid >> 2;
            int kq = tid & 3;
            cp_async16(wb + (uint32_t)(m * WROWB + kq * 16),
                       Wb + (size_t)m * HW_ + k0 + kq * 4);
        }
    };

    // ---- F prefetch first (independent of weights) ----
    load_F(0); CP_COMMIT();
    load_F(1); CP_COMMIT();
    load_F(2); CP_COMMIT();

    // ---- Phase A: this CTA's (b,m) histogram, in stage-3 F smem (unused yet)
    {
        float* hist = reinterpret_cast<float*>(smem + 3 * STAGE_BYTES);
        #pragma unroll 4
        for (int i = tid; i < HW_; i += 256) hist[i] = 0.0f;
        __syncthreads();

        const int bm = nblk + 4 * (b + 8 * ksp);    // bijection 0..255
        const float* cp = coords + (size_t)bm * P_ * 2;
        const float invP = 1.0f / (float)P_;
        const float s = (float)(HDIM_ - 1);

        #pragma unroll
        for (int p = tid; p < P_; p += 256) {
            float yn = cp[p * 2 + 0];
            float xn = cp[p * 2 + 1];
            float y = yn * s;
            float x = xn * s;
            float x0f = floorf(x), y0f = floorf(y);
            float wx = x - x0f, wy = y - y0f;
            int ix0 = min(max((int)x0f, 0), HDIM_ - 1);
            int ix1 = min(ix0 + 1, HDIM_ - 1);
            int iy0 = min(max((int)y0f, 0), HDIM_ - 1);
            int iy1 = min(iy0 + 1, HDIM_ - 1);
            atomicAdd(&hist[iy0 * HDIM_ + ix0], (1.0f - wx) * (1.0f - wy) * invP);
            atomicAdd(&hist[iy0 * HDIM_ + ix1], wx * (1.0f - wy) * invP);
            atomicAdd(&hist[iy1 * HDIM_ + ix0], (1.0f - wx) * wy * invP);
            atomicAdd(&hist[iy1 * HDIM_ + ix1], wx * wy * invP);
        }
        __syncthreads();

        float* wout = g_W + (size_t)bm * HW_;
        #pragma unroll 4
        for (int i = tid; i < HW_; i += 256)
            wout[i] = __uint_as_float(to_tf32(hist[i]));
    }

    // ---- Device-wide barrier (single wave: all 256 CTAs co-resident) ----
    __threadfence();
    __syncthreads();
    if (tid == 0) {
        atomicAdd(&g_bar, 1u);
        while (*((volatile unsigned int*)&g_bar) < NCTAS) {}
    }
    __syncthreads();
    __threadfence();    // acquire all g_W writes

    // ---- W prologue (group schedule F0 F1 F2 W0 W1 W2, validated in R7) ----
    load_W(0); CP_COMMIT();
    load_W(1); CP_COMMIT();
    load_W(2); CP_COMMIT();

    const int r = lane >> 2;            // 0..7
    const int c = lane & 3;             // 0..3
    const int chw = wid * 32;           // warp channel base within tile

    float d[2][4][4];
    #pragma unroll
    for (int t = 0; t < 2; t++)
        #pragma unroll
        for (int j = 0; j < 4; j++)
            #pragma unroll
            for (int e = 0; e < 4; e++) d[t][j][e] = 0.f;

    for (int i = 0; i < NCHUNK; i++) {
        CP_WAIT2();                 // chunk i resident (F(i) and W(i))
        __syncthreads();

        const float* fptr = reinterpret_cast<const float*>(smem + (i & (NSTAGE - 1)) * STAGE_BYTES);
        const float* wptr = fptr + KC * FSW;

        #pragma unroll
        for (int ks = 0; ks < KC / 8; ks++) {
            const int kr = ks * 8;
            // A = F fragments: 2 sets of 16 ch
            uint32_t a[2][4];
            #pragma unroll
            for (int t = 0; t < 2; t++) {
                const int chb = chw + t * 16;
                a[t][0] = to_tf32(fptr[(kr + c) * FSW + chb + r]);
                a[t][1] = to_tf32(fptr[(kr + c) * FSW + chb + r + 8]);
                a[t][2] = to_tf32(fptr[(kr + c + 4) * FSW + chb + r]);
                a[t][3] = to_tf32(fptr[(kr + c + 4) * FSW + chb + r + 8]);
            }
            // B = W fragments: 4 sets of 8 m (already tf32)
            uint32_t bf[4][2];
            #pragma unroll
            for (int j = 0; j < 4; j++) {
                bf[j][0] = __float_as_uint(wptr[(j * 8 + r) * WSW + kr + c]);
                bf[j][1] = __float_as_uint(wptr[(j * 8 + r) * WSW + kr + c + 4]);
            }
            #pragma unroll
            for (int t = 0; t < 2; t++)
                #pragma unroll
                for (int j = 0; j < 4; j++)
                    mma_tf32(d[t][j], a[t][0], a[t][1], a[t][2], a[t][3],
                             bf[j][0], bf[j][1]);
        }

        if (i + 3 < NCHUNK) { load_F(i + 3); load_W(i + 3); }
        CP_COMMIT();                // one group per iteration (may be empty)
    }

    // ---- write partials ----
    // D map per mma: thread (r,c) holds (ch=r, m=2c), (r, 2c+1), (r+8, 2c), (r+8, 2c+1)
    float* pb = g_part + ((size_t)(ksp * B_ + b)) * M_ * C_ + c0;
    #pragma unroll
    for (int t = 0; t < 2; t++) {
        const int ch = chw + t * 16 + r;
        #pragma unroll
        for (int j = 0; j < 4; j++) {
            int mA = j * 8 + 2 * c, mB = mA + 1;
            pb[(size_t)mA * C_ + ch]     = d[t][j][0];
            pb[(size_t)mB * C_ + ch]     = d[t][j][1];
            pb[(size_t)mA * C_ + ch + 8] = d[t][j][2];
            pb[(size_t)mB * C_ + ch + 8] = d[t][j][3];
        }
    }
}

// ---------------------------------------------------------------------------
// Pass 3: reduce KSPLIT partials -> d_out; also resets the global barrier
// (runs strictly after fused_mma, so no CTA is still polling it).
// ---------------------------------------------------------------------------
__global__ void __launch_bounds__(256) pass3_reduce(float* __restrict__ out)
{
    if (blockIdx.x == 0 && threadIdx.x == 0) g_bar = 0;
    const int total4 = B_ * M_ * C_ / 4;            // 65536 float4 slots
    int idx = blockIdx.x * 256 + threadIdx.x;
    if (idx >= total4) return;
    const float4* p = reinterpret_cast<const float4*>(g_part);
    float4 s = p[idx];
    #pragma unroll
    for (int k = 1; k < KSPLIT; k++) {
        float4 v = p[(size_t)k * total4 + idx];
        s.x += v.x; s.y += v.y; s.z += v.z; s.w += v.w;
    }
    reinterpret_cast<float4*>(out)[idx] = s;
}

// ---------------------------------------------------------------------------
extern "C" void kernel_launch(void* const* d_in, const int* in_sizes, int n_in,
                              void* d_out, int out_size)
{
    const float* feature = (const float*)d_in[0];
    const float* coords  = (const float*)d_in[1];
    if (n_in >= 2 && in_sizes[0] == B_ * M_ * P_ * 2) {
        feature = (const float*)d_in[1];
        coords  = (const float*)d_in[0];
    }

    cudaFuncSetAttribute(fused_mma, cudaFuncAttributeMaxDynamicSharedMemorySize, SMEM_TOTAL);

    dim3 g2(NBLKS, B_, KSPLIT);
    fused_mma<<<g2, 256, SMEM_TOTAL>>>(coords, feature);

    const int total4 = B_ * M_ * C_ / 4;            // 65536
    pass3_reduce<<<(total4 + 255) / 256, 256>>>((float*)d_out);
}

// round 10
// speedup vs baseline: 1.3067x; 1.0615x over previous
#include <cuda_runtime.h>
#include <cstdint>

// ---------------- problem constants ----------------
#define B_    8
#define HW_   4096
#define HDIM_ 64
#define C_    1024
#define M_    32
#define P_    512

// ---------------- GEMM tiling (R6-proven config) ----------------
#define CTILE   256                 // channels per CTA
#define NBLKS   (C_ / CTILE)        // 4
#define KSPLIT  8                   // K split across grid.z
#define KRANGE  (HW_ / KSPLIT)      // 512 k per CTA
#define KC      16                  // k (pixels) per chunk
#define NCHUNK  (KRANGE / KC)       // 32 chunks per CTA
#define NSTAGE  4
#define NCTAS   (NBLKS * B_ * KSPLIT)   // 256 == B_*M_ (one histogram per CTA)

// smem strides (words) — conflict-free fragment LDS, 16B-aligned rows
#define FSW 264                     // F row stride: 256 ch + 8 pad  (264%32=8)
#define WSW 36                      // W row stride: 16 k + 20 pad   (36%32=4)
#define FROWB (FSW * 4)             // 1056
#define WROWB (WSW * 4)             // 144
#define FBYTES (KC * FROWB)         // 16896
#define WBYTES (M_ * WROWB)         // 4608
#define STAGE_BYTES (FBYTES + WBYTES)       // 21504
#define SMEM_TOTAL (NSTAGE * STAGE_BYTES)   // 86016

// epilogue staging tile: [32 m][260 words]  (33280 B <= 2*STAGE_BYTES)
#define ESW 260

// Scratch: tf32(RNA)-rounded weights; device-wide barrier (self-resetting)
__device__ float g_W[(size_t)B_ * M_ * HW_];
__device__ unsigned int g_bar;
__device__ unsigned int g_bar2;

// ---------------- helpers ----------------
__device__ __forceinline__ uint32_t smem_u32(const void* p) {
    uint32_t a;
    asm("{ .reg .u64 t; cvta.to.shared.u64 t, %1; cvt.u32.u64 %0, t; }" : "=r"(a) : "l"(p));
    return a;
}
__device__ __forceinline__ void cp_async16(uint32_t dst, const void* src) {
    asm volatile("cp.async.cg.shared.global [%0], [%1], 16;" :: "r"(dst), "l"(src));
}
#define CP_COMMIT() asm volatile("cp.async.commit_group;" ::: "memory")
#define CP_WAIT2()  asm volatile("cp.async.wait_group 2;" ::: "memory")

__device__ __forceinline__ uint32_t to_tf32(float x) {
    uint32_t r;
    asm("cvt.rna.tf32.f32 %0, %1;" : "=r"(r) : "f"(x));
    return r;
}
__device__ __forceinline__ void red_add_v4(float* gptr, float4 v) {
    asm volatile("red.global.add.v4.f32 [%0], {%1, %2, %3, %4};"
                 :: "l"(gptr), "f"(v.x), "f"(v.y), "f"(v.z), "f"(v.w) : "memory");
}

// D[16ch x 8m] += A[16ch x 8k] * B[8k x 8m]   (tf32, fp32 accum)
__device__ __forceinline__ void mma_tf32(float* d,
                                         uint32_t a0, uint32_t a1, uint32_t a2, uint32_t a3,
                                         uint32_t b0, uint32_t b1) {
    asm volatile(
        "mma.sync.aligned.m16n8k8.row.col.f32.tf32.tf32.f32 "
        "{%0,%1,%2,%3}, {%4,%5,%6,%7}, {%8,%9}, {%0,%1,%2,%3};"
        : "+f"(d[0]), "+f"(d[1]), "+f"(d[2]), "+f"(d[3])
        : "r"(a0), "r"(a1), "r"(a2), "r"(a3), "r"(b0), "r"(b1));
}

// ---------------------------------------------------------------------------
// Single fused kernel:
//   phase A: one (b,m) weight histogram per CTA + zero this CTA's out slice
//   device-wide barrier (single wave: 256 CTAs, 2/SM x 148 = 296 slots)
//   phase B: tf32 HMMA GEMM over K-split, epilogue = red.global.add.v4.f32
// ---------------------------------------------------------------------------
__global__ void __launch_bounds__(256, 2) fused_mma(
    const float* __restrict__ coords,   // [B, M, P, 2]
    const float* __restrict__ F,        // [B, HW, C]
    float* __restrict__ out)            // [B, M, 1, C]
{
    extern __shared__ char smem[];
    const uint32_t sbase = smem_u32(smem);

    const int tid  = threadIdx.x;
    const int lane = tid & 31;
    const int wid  = tid >> 5;          // 0..7
    const int nblk = blockIdx.x;        // 0..3
    const int b    = blockIdx.y;        // 0..7
    const int ksp  = blockIdx.z;        // 0..7
    const int c0   = nblk * CTILE;
    const int kbase = ksp * KRANGE;

    const float* Fb = F + ((size_t)b * HW_ + kbase) * C_ + c0;
    const float* Wb = g_W + (size_t)b * M_ * HW_ + kbase;

    // F tile loader: [16k x 256ch]
    auto load_F = [&](int chunk) {
        const int s  = chunk & (NSTAGE - 1);
        const int k0 = chunk * KC;
        const uint32_t fb = sbase + s * STAGE_BYTES;
        #pragma unroll
        for (int h = 0; h < 4; h++) {
            int unit = tid + h * 256;
            int row = unit >> 6;        // local k 0..15
            int uc  = unit & 63;        // 16B unit within 256-ch row
            cp_async16(fb + (uint32_t)(row * FROWB + uc * 16),
                       Fb + (size_t)(k0 + row) * C_ + uc * 4);
        }
    };
    // W tile loader: [32m x 16k]
    auto load_W = [&](int chunk) {
        const int s  = chunk & (NSTAGE - 1);
        const int k0 = chunk * KC;
        const uint32_t wb = sbase + s * STAGE_BYTES + FBYTES;
        if (tid < 128) {
            int m  = tid >> 2;
            int kq = tid & 3;
            cp_async16(wb + (uint32_t)(m * WROWB + kq * 16),
                       Wb + (size_t)m * HW_ + k0 + kq * 4);
        }
    };

    // ---- F prefetch first (independent of weights) ----
    load_F(0); CP_COMMIT();
    load_F(1); CP_COMMIT();
    load_F(2); CP_COMMIT();

    const int flat = nblk + NBLKS * (b + B_ * ksp);     // bijection 0..255

    // ---- Phase A: histogram for (b,m)=flat, in stage-3 F smem (unused yet),
    //      plus zero this CTA's 1024-float slice of the output.
    {
        // zero output slice (one float4 per thread)
        float4* oz = reinterpret_cast<float4*>(out + (size_t)flat * 1024) ;
        oz[tid] = make_float4(0.f, 0.f, 0.f, 0.f);

        float* hist = reinterpret_cast<float*>(smem + 3 * STAGE_BYTES);
        #pragma unroll 4
        for (int i = tid; i < HW_; i += 256) hist[i] = 0.0f;
        __syncthreads();

        const float* cp = coords + (size_t)flat * P_ * 2;
        const float invP = 1.0f / (float)P_;
        const float s = (float)(HDIM_ - 1);

        #pragma unroll
        for (int p = tid; p < P_; p += 256) {
            float yn = cp[p * 2 + 0];
            float xn = cp[p * 2 + 1];
            float y = yn * s;
            float x = xn * s;
            float x0f = floorf(x), y0f = floorf(y);
            float wx = x - x0f, wy = y - y0f;
            int ix0 = min(max((int)x0f, 0), HDIM_ - 1);
            int ix1 = min(ix0 + 1, HDIM_ - 1);
            int iy0 = min(max((int)y0f, 0), HDIM_ - 1);
            int iy1 = min(iy0 + 1, HDIM_ - 1);
            atomicAdd(&hist[iy0 * HDIM_ + ix0], (1.0f - wx) * (1.0f - wy) * invP);
            atomicAdd(&hist[iy0 * HDIM_ + ix1], wx * (1.0f - wy) * invP);
            atomicAdd(&hist[iy1 * HDIM_ + ix0], (1.0f - wx) * wy * invP);
            atomicAdd(&hist[iy1 * HDIM_ + ix1], wx * wy * invP);
        }
        __syncthreads();

        float* wout = g_W + (size_t)flat * HW_;
        #pragma unroll 4
        for (int i = tid; i < HW_; i += 256)
            wout[i] = __uint_as_float(to_tf32(hist[i]));
    }

    // ---- Device-wide barrier (single wave: all 256 CTAs co-resident) ----
    __threadfence();
    __syncthreads();
    if (tid == 0) {
        atomicAdd(&g_bar, 1u);
        while (*((volatile unsigned int*)&g_bar) < NCTAS) {}
    }
    __syncthreads();
    __threadfence();    // acquire all g_W writes + out zeroing

    // ---- W prologue (group schedule F0 F1 F2 W0 W1 W2, validated R7/R9) ----
    load_W(0); CP_COMMIT();
    load_W(1); CP_COMMIT();
    load_W(2); CP_COMMIT();

    const int r = lane >> 2;            // 0..7
    const int c = lane & 3;             // 0..3
    const int chw = wid * 32;           // warp channel base within tile

    float d[2][4][4];
    #pragma unroll
    for (int t = 0; t < 2; t++)
        #pragma unroll
        for (int j = 0; j < 4; j++)
            #pragma unroll
            for (int e = 0; e < 4; e++) d[t][j][e] = 0.f;

    for (int i = 0; i < NCHUNK; i++) {
        CP_WAIT2();                 // chunk i resident (F(i) and W(i))
        __syncthreads();

        const float* fptr = reinterpret_cast<const float*>(smem + (i & (NSTAGE - 1)) * STAGE_BYTES);
        const float* wptr = fptr + KC * FSW;

        #pragma unroll
        for (int ks = 0; ks < KC / 8; ks++) {
            const int kr = ks * 8;
            // A = F fragments: 2 sets of 16 ch
            uint32_t a[2][4];
            #pragma unroll
            for (int t = 0; t < 2; t++) {
                const int chb = chw + t * 16;
                a[t][0] = to_tf32(fptr[(kr + c) * FSW + chb + r]);
                a[t][1] = to_tf32(fptr[(kr + c) * FSW + chb + r + 8]);
                a[t][2] = to_tf32(fptr[(kr + c + 4) * FSW + chb + r]);
                a[t][3] = to_tf32(fptr[(kr + c + 4) * FSW + chb + r + 8]);
            }
            // B = W fragments: 4 sets of 8 m (already tf32)
            uint32_t bf[4][2];
            #pragma unroll
            for (int j = 0; j < 4; j++) {
                bf[j][0] = __float_as_uint(wptr[(j * 8 + r) * WSW + kr + c]);
                bf[j][1] = __float_as_uint(wptr[(j * 8 + r) * WSW + kr + c + 4]);
            }
            #pragma unroll
            for (int t = 0; t < 2; t++)
                #pragma unroll
                for (int j = 0; j < 4; j++)
                    mma_tf32(d[t][j], a[t][0], a[t][1], a[t][2], a[t][3],
                             bf[j][0], bf[j][1]);
        }

        if (i + 3 < NCHUNK) { load_F(i + 3); load_W(i + 3); }
        CP_COMMIT();                // one group per iteration (may be empty)
    }

    // ---- epilogue: stage D[32m x 256ch] in smem, then coalesced v4 L2-reductions
    __syncthreads();                // all compute done; reuse stage 0/1 smem
    {
        float* etile = reinterpret_cast<float*>(smem);      // [32][ESW]
        // D map per mma: thread (r,c) holds (ch, m=2c), (ch, 2c+1), (ch+8, 2c), (ch+8, 2c+1)
        #pragma unroll
        for (int t = 0; t < 2; t++) {
            const int ch = chw + t * 16 + r;
            #pragma unroll
            for (int j = 0; j < 4; j++) {
                int mA = j * 8 + 2 * c, mB = mA + 1;
                etile[mA * ESW + ch]     = d[t][j][0];
                etile[mB * ESW + ch]     = d[t][j][1];
                etile[mA * ESW + ch + 8] = d[t][j][2];
                etile[mB * ESW + ch + 8] = d[t][j][3];
            }
        }
        __syncthreads();

        float* ob = out + (size_t)b * M_ * C_ + c0;
        #pragma unroll
        for (int h = 0; h < 8; h++) {
            int idx = tid + h * 256;        // 0..2047
            int m = idx >> 6;               // 0..31
            int q = idx & 63;               // float4 slot within 256 ch
            const float4 v = *reinterpret_cast<const float4*>(etile + m * ESW + q * 4);
            red_add_v4(ob + (size_t)m * C_ + q * 4, v);
        }
    }

    // ---- barrier self-reset (safe: all CTAs are past the first barrier) ----
    __syncthreads();
    if (tid == 0) {
        unsigned int old = atomicAdd(&g_bar2, 1u);
        if (old == NCTAS - 1) {
            g_bar = 0;
            g_bar2 = 0;
            __threadfence();
        }
    }
}

// ---------------------------------------------------------------------------
extern "C" void kernel_launch(void* const* d_in, const int* in_sizes, int n_in,
                              void* d_out, int out_size)
{
    const float* feature = (const float*)d_in[0];
    const float* coords  = (const float*)d_in[1];
    if (n_in >= 2 && in_sizes[0] == B_ * M_ * P_ * 2) {
        feature = (const float*)d_in[1];
        coords  = (const float*)d_in[0];
    }

    cudaFuncSetAttribute(fused_mma, cudaFuncAttributeMaxDynamicSharedMemorySize, SMEM_TOTAL);

    dim3 g2(NBLKS, B_, KSPLIT);
    fused_mma<<<g2, 256, SMEM_TOTAL>>>(coords, feature, (float*)d_out);
}